// round 14
// baseline (speedup 1.0000x reference)
#include <cuda_runtime.h>
#include <cuda_bf16.h>
#include <cstdint>
#include <float.h>

#define DIMS 256
#define NE   8192
#define NTOK 16384

// Output layout (float32, concatenated in reference return order)
#define OFF_Q    0
#define OFF_DIFF 4194304
#define OFF_IND  4194305
#define OFF_OH   4210689
#define OFF_ES   4218881
#define OUT_TOT  6316033

#define CAP    512
#define SURV   64
#define MARGIN 12.0f

// Phase A tiling (fp8) — R8/R13 warp geometry, finer grid for load balance
#define TM     128
#define TN     128
#define NSPLIT 4
#define NCHUNK (NE / TN / NSPLIT)   // 16
#define ROWB   272

// ---------------- device scratch (static, no runtime allocs) ----------------
__device__ uint8_t  g_x8[NTOK * DIMS];
__device__ uint8_t  g_e8[NE * DIMS];
__device__ float    g_ebT[NE * DIMS];
__device__ float    g_enorm[NE];
__device__ int      g_ccnt[NTOK];
__device__ uint32_t g_gmin[NTOK];              // encoded approx global min
__device__ float    g_cs[(size_t)NTOK * CAP];
__device__ int      g_ci[(size_t)NTOK * CAP];

// ---------------- baseline-PTX helpers --------------------------------------
__device__ __forceinline__ uint32_t smem_u32(const void* p) {
    uint32_t a;
    asm("{ .reg .u64 t; cvta.to.shared.u64 t, %1; cvt.u32.u64 %0, t; }"
        : "=r"(a) : "l"(p));
    return a;
}
__device__ __forceinline__ void cp_async16(uint32_t dst, const void* src) {
    asm volatile("cp.async.cg.shared.global [%0], [%1], 16;"
                 :: "r"(dst), "l"(src) : "memory");
}
__device__ __forceinline__ void cp_commit() {
    asm volatile("cp.async.commit_group;" ::: "memory");
}
__device__ __forceinline__ void cp_wait0() {
    asm volatile("cp.async.wait_group 0;" ::: "memory");
}
__device__ __forceinline__ void ldsm_x4(uint32_t* r, uint32_t addr) {
    asm volatile("ldmatrix.sync.aligned.m8n8.x4.shared.b16 {%0,%1,%2,%3}, [%4];"
                 : "=r"(r[0]), "=r"(r[1]), "=r"(r[2]), "=r"(r[3]) : "r"(addr));
}
__device__ __forceinline__ void mma_fp8(float* c, const uint32_t* a,
                                        uint32_t b0, uint32_t b1) {
    asm volatile(
        "mma.sync.aligned.m16n8k32.row.col.f32.e4m3.e4m3.f32 "
        "{%0,%1,%2,%3}, {%4,%5,%6,%7}, {%8,%9}, {%0,%1,%2,%3};"
        : "+f"(c[0]), "+f"(c[1]), "+f"(c[2]), "+f"(c[3])
        : "r"(a[0]), "r"(a[1]), "r"(a[2]), "r"(a[3]), "r"(b0), "r"(b1));
}
__device__ __forceinline__ uint16_t f2_e4m3(float lo, float hi) {
    uint16_t r;
    asm("cvt.rn.satfinite.e4m3x2.f32 %0, %1, %2;" : "=h"(r) : "f"(hi), "f"(lo));
    return r;
}
__device__ __forceinline__ uint32_t encf(float f) {
    uint32_t b = __float_as_uint(f);
    return (b & 0x80000000u) ? ~b : (b | 0x80000000u);
}
__device__ __forceinline__ float decf(uint32_t u) {
    uint32_t b = (u & 0x80000000u) ? (u ^ 0x80000000u) : ~u;
    return __uint_as_float(b);
}

// ---------------- fused prep: conv_x + zero-init + transpose ----------------
#define CONV_BLKS 1024
__global__ void prep_kernel(const float* __restrict__ x,
                            const float* __restrict__ embed,
                            float* __restrict__ out) {
    if (blockIdx.x < CONV_BLKS) {
        const int gtid = blockIdx.x * blockDim.x + threadIdx.x;
        const int gstride = CONV_BLKS * blockDim.x;
        size_t i = (size_t)gtid * 16;
        if (i < (size_t)NTOK * DIMS) {
            uint4 o;
            uint32_t* op = (uint32_t*)&o;
#pragma unroll
            for (int j = 0; j < 4; j++) {
                float4 v = *(const float4*)(x + i + j * 4);
                op[j] = (uint32_t)f2_e4m3(v.x, v.y) |
                        ((uint32_t)f2_e4m3(v.z, v.w) << 16);
            }
            *(uint4*)(g_x8 + i) = o;
        }
        for (int j = gtid; j < OUT_TOT - OFF_DIFF; j += gstride)
            out[OFF_DIFF + j] = 0.0f;
        for (int j = gtid; j < NTOK; j += gstride) {
            g_ccnt[j] = 0;
            g_gmin[j] = 0xFFFFFFFFu;
        }
        for (int j = gtid; j < NE; j += gstride) g_enorm[j] = 0.0f;
    } else {
        __shared__ float ts[32][33];
        const int bb = blockIdx.x - CONV_BLKS;
        const int n0 = (bb & 255) * 32;
        const int d0 = (bb >> 8) * 32;
        const int tx = threadIdx.x & 31;
        const int ty = threadIdx.x >> 5;
        for (int r = ty; r < 32; r += 8)
            ts[r][tx] = embed[(size_t)(d0 + r) * NE + n0 + tx];
        __syncthreads();
        const int code = threadIdx.x >> 3;
        const int dg   = threadIdx.x & 7;
        float v0 = ts[dg * 4 + 0][code];
        float v1 = ts[dg * 4 + 1][code];
        float v2 = ts[dg * 4 + 2][code];
        float v3 = ts[dg * 4 + 3][code];
        size_t o = (size_t)(n0 + code) * DIMS + d0 + dg * 4;
        *(float4*)(g_ebT + o) = make_float4(v0, v1, v2, v3);
        *(uint32_t*)(g_e8 + o) = (uint32_t)f2_e4m3(v0, v1) |
                                 ((uint32_t)f2_e4m3(v2, v3) << 16);
        atomicAdd(&g_enorm[n0 + code], v0 * v0 + v1 * v1 + v2 * v2 + v3 * v3);
    }
}

// ---------------- Phase A: FP8 MMA GEMM + candidate collection --------------
#define AS_OFF   0
#define BS_OFF   (TM * ROWB)
#define BS_SZ    (TN * ROWB)
#define ES_OFF   (BS_OFF + 2 * BS_SZ)
#define MIN_OFF  (ES_OFF + 2 * TN * 4)
#define SMEM_TOT (MIN_OFF + TM * 4)             // 105984

__global__ __launch_bounds__(256, 2) void phaseA_kernel() {
    extern __shared__ __align__(128) char smem[];
    const uint32_t sb = smem_u32(smem);
    uint32_t* smin = (uint32_t*)(smem + MIN_OFF);
    const int tid  = threadIdx.x;
    const int lane = tid & 31;
    const int wid  = tid >> 5;
    const int warpM = wid & 3;
    const int warpN = wid >> 2;
    const int gid  = lane >> 2;
    const int tidg = lane & 3;
    const int m0   = blockIdx.x * TM;
    const int c0   = blockIdx.y * NCHUNK;

    if (tid < TM) smin[tid] = 0xFFFFFFFFu;

    {
#pragma unroll
        for (int j = 0; j < 8; j++) {
            int i = tid + j * 256;
            int r = i >> 4, c = i & 15;
            cp_async16(sb + AS_OFF + r * ROWB + c * 16,
                       g_x8 + (size_t)(m0 + r) * 256 + c * 16);
        }
#pragma unroll
        for (int j = 0; j < 8; j++) {
            int i = tid + j * 256;
            int r = i >> 4, c = i & 15;
            cp_async16(sb + BS_OFF + r * ROWB + c * 16,
                       g_e8 + (size_t)c0 * TN * 256 + (size_t)r * 256 + c * 16);
        }
        if (tid < 32)
            cp_async16(sb + ES_OFF + tid * 16,
                       (const char*)(g_enorm + c0 * TN) + tid * 16);
        cp_commit();
    }

    uint32_t addrA[2];
#pragma unroll
    for (int mt = 0; mt < 2; mt++) {
        int r = warpM * 32 + mt * 16 + ((lane >> 3) & 1) * 8 + (lane & 7);
        addrA[mt] = sb + AS_OFF + r * ROWB + ((lane >> 4) * 16);
    }
    uint32_t rowoffB[4];
#pragma unroll
    for (int g = 0; g < 4; g++) {
        int r = warpN * 64 + g * 16 + (lane >> 4) * 8 + (lane & 7);
        rowoffB[g] = r * ROWB + ((lane >> 3) & 1) * 16;
    }

    const int tl0 = warpM * 32 + gid;

    for (int s = 0; s < NCHUNK; s++) {
        cp_wait0();
        __syncthreads();

        if (s + 1 < NCHUNK) {
            const uint8_t* bsrc = g_e8 + (size_t)(c0 + s + 1) * TN * 256;
            uint32_t bdst = sb + BS_OFF + ((s + 1) & 1) * BS_SZ;
#pragma unroll
            for (int j = 0; j < 8; j++) {
                int i = tid + j * 256;
                int r = i >> 4, c = i & 15;
                cp_async16(bdst + r * ROWB + c * 16, bsrc + (size_t)r * 256 + c * 16);
            }
            if (tid < 32)
                cp_async16(sb + ES_OFF + ((s + 1) & 1) * 512 + tid * 16,
                           (const char*)(g_enorm + (size_t)(c0 + s + 1) * TN) + tid * 16);
            cp_commit();
        }

        const int b = s & 1;
        const uint32_t bbase = sb + BS_OFF + b * BS_SZ;

        float acc[2][8][4];
#pragma unroll
        for (int mt = 0; mt < 2; mt++)
#pragma unroll
            for (int nt = 0; nt < 8; nt++)
#pragma unroll
                for (int q = 0; q < 4; q++) acc[mt][nt][q] = 0.0f;

#pragma unroll
        for (int k = 0; k < 8; k++) {
            uint32_t afr[2][4], bfr[4][4];
            ldsm_x4(afr[0], addrA[0] + k * 32);
            ldsm_x4(afr[1], addrA[1] + k * 32);
#pragma unroll
            for (int g = 0; g < 4; g++)
                ldsm_x4(bfr[g], bbase + rowoffB[g] + k * 32);
#pragma unroll
            for (int mt = 0; mt < 2; mt++)
#pragma unroll
                for (int nt = 0; nt < 8; nt++)
                    mma_fp8(acc[mt][nt], afr[mt],
                            bfr[nt >> 1][(nt & 1) * 2],
                            bfr[nt >> 1][(nt & 1) * 2 + 1]);
        }

        // ---- single-pass epilogue: in-place scores + lagged prefix-min ----
        const float2* ep = (const float2*)(smem + ES_OFF + b * 512);
        float cmin[2][2];
        cmin[0][0] = cmin[0][1] = cmin[1][0] = cmin[1][1] = FLT_MAX;
#pragma unroll
        for (int nt = 0; nt < 8; nt++) {
            const float2 e = ep[(warpN * 64 + nt * 8 + tidg * 2) >> 1];
#pragma unroll
            for (int mt = 0; mt < 2; mt++) {
                float s00 = fmaf(-2.0f, acc[mt][nt][0], e.x);
                float s01 = fmaf(-2.0f, acc[mt][nt][1], e.y);
                float s10 = fmaf(-2.0f, acc[mt][nt][2], e.x);
                float s11 = fmaf(-2.0f, acc[mt][nt][3], e.y);
                acc[mt][nt][0] = s00; acc[mt][nt][1] = s01;
                acc[mt][nt][2] = s10; acc[mt][nt][3] = s11;
                cmin[mt][0] = fminf(cmin[mt][0], fminf(s00, s01));
                cmin[mt][1] = fminf(cmin[mt][1], fminf(s10, s11));
            }
        }
        float wmin[2][2];
#pragma unroll
        for (int mt = 0; mt < 2; mt++)
#pragma unroll
            for (int h = 0; h < 2; h++) {
                float v = cmin[mt][h];
                v = fminf(v, __shfl_xor_sync(0xffffffffu, v, 1));
                v = fminf(v, __shfl_xor_sync(0xffffffffu, v, 2));
                wmin[mt][h] = v;
                if (tidg == 0) {
                    const int tl = tl0 + mt * 16 + h * 8;
                    const uint32_t u = encf(v);
                    if (u < smin[tl]) atomicMin(&smin[tl], u);
                }
            }
        if (s == 0) __syncthreads();   // exact threshold for first chunk

        const int cgb = (c0 + s) * TN + warpN * 64 + tidg * 2;
#pragma unroll
        for (int mt = 0; mt < 2; mt++) {
            const int t0 = m0 + tl0 + mt * 16;
            const int t1 = t0 + 8;
            const float thr0 =
                fminf(decf(smin[tl0 + mt * 16]), wmin[mt][0]) + MARGIN;
            const float thr1 =
                fminf(decf(smin[tl0 + mt * 16 + 8]), wmin[mt][1]) + MARGIN;

            if (cmin[mt][0] <= thr0) {
#pragma unroll
                for (int nt = 0; nt < 8; nt++) {
                    if (fminf(acc[mt][nt][0], acc[mt][nt][1]) <= thr0) {
                        const int cg = cgb + nt * 8;
                        if (acc[mt][nt][0] <= thr0) {
                            int pos = atomicAdd(&g_ccnt[t0], 1);
                            if (pos < CAP) { g_cs[(size_t)t0 * CAP + pos] = acc[mt][nt][0];
                                             g_ci[(size_t)t0 * CAP + pos] = cg; }
                        }
                        if (acc[mt][nt][1] <= thr0) {
                            int pos = atomicAdd(&g_ccnt[t0], 1);
                            if (pos < CAP) { g_cs[(size_t)t0 * CAP + pos] = acc[mt][nt][1];
                                             g_ci[(size_t)t0 * CAP + pos] = cg + 1; }
                        }
                    }
                }
            }
            if (cmin[mt][1] <= thr1) {
#pragma unroll
                for (int nt = 0; nt < 8; nt++) {
                    if (fminf(acc[mt][nt][2], acc[mt][nt][3]) <= thr1) {
                        const int cg = cgb + nt * 8;
                        if (acc[mt][nt][2] <= thr1) {
                            int pos = atomicAdd(&g_ccnt[t1], 1);
                            if (pos < CAP) { g_cs[(size_t)t1 * CAP + pos] = acc[mt][nt][2];
                                             g_ci[(size_t)t1 * CAP + pos] = cg; }
                        }
                        if (acc[mt][nt][3] <= thr1) {
                            int pos = atomicAdd(&g_ccnt[t1], 1);
                            if (pos < CAP) { g_cs[(size_t)t1 * CAP + pos] = acc[mt][nt][3];
                                             g_ci[(size_t)t1 * CAP + pos] = cg + 1; }
                        }
                    }
                }
            }
        }
    }

    // publish per-token approx min (phaseC pruning threshold)
    __syncthreads();
    if (tid < TM) {
        uint32_t u = smin[tid];
        if (u < g_gmin[m0 + tid]) atomicMin(&g_gmin[m0 + tid], u);
    }
}

// ---------------- Phase C: parallel prune + exact rescore + scatter ---------
__global__ __launch_bounds__(256) void phaseC_kernel(
    const float* __restrict__ x, float* __restrict__ out)
{
    __shared__ float blk_diff;
    __shared__ int surv[8][SURV];
    const int lane = threadIdx.x & 31;
    const int w = threadIdx.x >> 5;
    const int t = blockIdx.x * 8 + w;

    if (threadIdx.x == 0) blk_diff = 0.0f;
    __syncthreads();

    float xr[8];
    *(float4*)(xr)     = *(const float4*)(x + (size_t)t * DIMS + lane * 8);
    *(float4*)(xr + 4) = *(const float4*)(x + (size_t)t * DIMS + lane * 8 + 4);

    const int n = g_ccnt[t];
    float bs = FLT_MAX;
    int bi = NE;
    bool fallback = (n > CAP);
    int cnt = 0;

    if (!fallback) {
        // parallel prune: 32 lanes test strided candidates, ballot-compact
        const float thr = decf(g_gmin[t]) + MARGIN;
        const float* cs = g_cs + (size_t)t * CAP;
        const int*   ci = g_ci + (size_t)t * CAP;
        for (int base = 0; base < n; base += 32) {
            const int i = base + lane;
            const bool act = i < n;
            const float sv = act ? cs[i] : FLT_MAX;
            const bool keep = act && (sv <= thr);
            const int kv = keep ? ci[i] : 0;
            const uint32_t mask = __ballot_sync(0xffffffffu, keep);
            const int idx = cnt + __popc(mask & ((1u << lane) - 1));
            if (keep && idx < SURV) surv[w][idx] = kv;
            cnt += __popc(mask);
        }
        if (cnt > SURV) fallback = true;
        __syncwarp();
    }

    if (fallback) {
        // exhaustive exact scan (probabilistically unreachable)
        for (int k = lane; k < NE; k += 32) {
            const float* er = g_ebT + (size_t)k * DIMS;
            const float* xp = x + (size_t)t * DIMS;
            float dot = 0.0f;
            for (int d = 0; d < DIMS; d += 4) {
                float4 xv = *(const float4*)(xp + d);
                float4 ev = *(const float4*)(er + d);
                dot += xv.x * ev.x + xv.y * ev.y + xv.z * ev.z + xv.w * ev.w;
            }
            float s = g_enorm[k] - 2.0f * dot;
            if (s < bs || (s == bs && k < bi)) { bs = s; bi = k; }
        }
        for (int off = 16; off; off >>= 1) {
            float ov = __shfl_xor_sync(0xffffffffu, bs, off);
            int oi = __shfl_xor_sync(0xffffffffu, bi, off);
            if (ov < bs || (ov == bs && oi < bi)) { bs = ov; bi = oi; }
        }
    } else {
        // warp-cooperative exact dot on each survivor (~2-5 per token)
        for (int j = 0; j < cnt; j++) {
            const int k = surv[w][j];
            const float* er = g_ebT + (size_t)k * DIMS + lane * 8;
            float4 e0 = *(const float4*)(er);
            float4 e1 = *(const float4*)(er + 4);
            float d = xr[0] * e0.x + xr[1] * e0.y + xr[2] * e0.z + xr[3] * e0.w
                    + xr[4] * e1.x + xr[5] * e1.y + xr[6] * e1.z + xr[7] * e1.w;
            for (int off = 16; off; off >>= 1)
                d += __shfl_xor_sync(0xffffffffu, d, off);
            float s = g_enorm[k] - 2.0f * d;
            if (s < bs || (s == bs && k < bi)) { bs = s; bi = k; }
        }
    }

    // ---- fused scatter: quantize row, diff, onehot, embed_sum, ind ----
    const float* qr = g_ebT + (size_t)bi * DIMS + lane * 8;
    float4 q0 = *(const float4*)(qr);
    float4 q1 = *(const float4*)(qr + 4);
    *(float4*)(out + OFF_Q + (size_t)t * DIMS + lane * 8)     = q0;
    *(float4*)(out + OFF_Q + (size_t)t * DIMS + lane * 8 + 4) = q1;

    float qv[8] = {q0.x, q0.y, q0.z, q0.w, q1.x, q1.y, q1.z, q1.w};
    float dp = 0.0f;
#pragma unroll
    for (int j = 0; j < 8; j++) {
        float dd = qv[j] - xr[j];
        dp += dd * dd;
        atomicAdd(out + OFF_ES + (size_t)(lane * 8 + j) * NE + bi, xr[j]);
    }
    for (int off = 16; off; off >>= 1)
        dp += __shfl_down_sync(0xffffffffu, dp, off);
    if (lane == 0) {
        atomicAdd(&blk_diff, dp);
        atomicAdd(out + OFF_OH + bi, 1.0f);
        out[OFF_IND + t] = (float)bi;
    }
    __syncthreads();
    if (threadIdx.x == 0)
        atomicAdd(out + OFF_DIFF, blk_diff * (1.0f / (float)(NTOK * DIMS)));
}

// ---------------------------------------------------------------------------
extern "C" void kernel_launch(void* const* d_in, const int* in_sizes, int n_in,
                              void* d_out, int out_size)
{
    const float* x = (const float*)d_in[0];
    const float* embed = (const float*)d_in[1];
    if (n_in >= 2 && in_sizes[0] == DIMS * NE && in_sizes[1] == NTOK * DIMS) {
        const float* tmp = x; x = embed; embed = tmp;
    }
    float* out = (float*)d_out;

    cudaFuncSetAttribute(phaseA_kernel,
                         cudaFuncAttributeMaxDynamicSharedMemorySize, SMEM_TOT);

    prep_kernel<<<CONV_BLKS + 2048, 256>>>(x, embed, out);
    phaseA_kernel<<<dim3(NTOK / TM, NSPLIT), 256, SMEM_TOT>>>();
    phaseC_kernel<<<NTOK / 8, 256>>>(x, out);
}

// round 15
// speedup vs baseline: 1.0563x; 1.0563x over previous
#include <cuda_runtime.h>
#include <cuda_bf16.h>
#include <cstdint>
#include <float.h>

#define DIMS 256
#define NE   8192
#define NTOK 16384

// Output layout (float32, concatenated in reference return order)
#define OFF_Q    0
#define OFF_DIFF 4194304
#define OFF_IND  4194305
#define OFF_OH   4210689
#define OFF_ES   4218881
#define OUT_TOT  6316033

#define CAP    512
#define SURV   64
#define MARGIN 12.0f

// Phase A tiling (fp8) — R8/R13 geometry (365.5us champion)
#define TM     128
#define TN     128
#define NSPLIT 2
#define NCHUNK (NE / TN / NSPLIT)   // 32
#define ROWB   272

// ---------------- device scratch (static, no runtime allocs) ----------------
__device__ uint8_t  g_x8[NTOK * DIMS];
__device__ uint8_t  g_e8[NE * DIMS];
__device__ float    g_ebT[NE * DIMS];
__device__ float    g_enorm[NE];
__device__ int      g_ccnt[NTOK];
__device__ uint32_t g_gmin[NTOK];              // encoded approx global min
__device__ float    g_cs[(size_t)NTOK * CAP];
__device__ int      g_ci[(size_t)NTOK * CAP];

// ---------------- baseline-PTX helpers --------------------------------------
__device__ __forceinline__ uint32_t smem_u32(const void* p) {
    uint32_t a;
    asm("{ .reg .u64 t; cvta.to.shared.u64 t, %1; cvt.u32.u64 %0, t; }"
        : "=r"(a) : "l"(p));
    return a;
}
__device__ __forceinline__ void cp_async16(uint32_t dst, const void* src) {
    asm volatile("cp.async.cg.shared.global [%0], [%1], 16;"
                 :: "r"(dst), "l"(src) : "memory");
}
__device__ __forceinline__ void cp_commit() {
    asm volatile("cp.async.commit_group;" ::: "memory");
}
__device__ __forceinline__ void cp_wait0() {
    asm volatile("cp.async.wait_group 0;" ::: "memory");
}
__device__ __forceinline__ void ldsm_x4(uint32_t* r, uint32_t addr) {
    asm volatile("ldmatrix.sync.aligned.m8n8.x4.shared.b16 {%0,%1,%2,%3}, [%4];"
                 : "=r"(r[0]), "=r"(r[1]), "=r"(r[2]), "=r"(r[3]) : "r"(addr));
}
__device__ __forceinline__ void mma_fp8(float* c, const uint32_t* a,
                                        uint32_t b0, uint32_t b1) {
    asm volatile(
        "mma.sync.aligned.m16n8k32.row.col.f32.e4m3.e4m3.f32 "
        "{%0,%1,%2,%3}, {%4,%5,%6,%7}, {%8,%9}, {%0,%1,%2,%3};"
        : "+f"(c[0]), "+f"(c[1]), "+f"(c[2]), "+f"(c[3])
        : "r"(a[0]), "r"(a[1]), "r"(a[2]), "r"(a[3]), "r"(b0), "r"(b1));
}
__device__ __forceinline__ uint16_t f2_e4m3(float lo, float hi) {
    uint16_t r;
    asm("cvt.rn.satfinite.e4m3x2.f32 %0, %1, %2;" : "=h"(r) : "f"(hi), "f"(lo));
    return r;
}
__device__ __forceinline__ uint32_t encf(float f) {
    uint32_t b = __float_as_uint(f);
    return (b & 0x80000000u) ? ~b : (b | 0x80000000u);
}
__device__ __forceinline__ float decf(uint32_t u) {
    uint32_t b = (u & 0x80000000u) ? (u ^ 0x80000000u) : ~u;
    return __uint_as_float(b);
}

// ---------------- fused prep: conv_x + zero-init + transpose ----------------
#define CONV_BLKS 1024
__global__ void prep_kernel(const float* __restrict__ x,
                            const float* __restrict__ embed,
                            float* __restrict__ out) {
    if (blockIdx.x < CONV_BLKS) {
        const int gtid = blockIdx.x * blockDim.x + threadIdx.x;
        const int gstride = CONV_BLKS * blockDim.x;
        size_t i = (size_t)gtid * 16;
        if (i < (size_t)NTOK * DIMS) {
            uint4 o;
            uint32_t* op = (uint32_t*)&o;
#pragma unroll
            for (int j = 0; j < 4; j++) {
                float4 v = *(const float4*)(x + i + j * 4);
                op[j] = (uint32_t)f2_e4m3(v.x, v.y) |
                        ((uint32_t)f2_e4m3(v.z, v.w) << 16);
            }
            *(uint4*)(g_x8 + i) = o;
        }
        for (int j = gtid; j < OUT_TOT - OFF_DIFF; j += gstride)
            out[OFF_DIFF + j] = 0.0f;
        for (int j = gtid; j < NTOK; j += gstride) {
            g_ccnt[j] = 0;
            g_gmin[j] = 0xFFFFFFFFu;
        }
        for (int j = gtid; j < NE; j += gstride) g_enorm[j] = 0.0f;
    } else {
        __shared__ float ts[32][33];
        const int bb = blockIdx.x - CONV_BLKS;
        const int n0 = (bb & 255) * 32;
        const int d0 = (bb >> 8) * 32;
        const int tx = threadIdx.x & 31;
        const int ty = threadIdx.x >> 5;
        for (int r = ty; r < 32; r += 8)
            ts[r][tx] = embed[(size_t)(d0 + r) * NE + n0 + tx];
        __syncthreads();
        const int code = threadIdx.x >> 3;
        const int dg   = threadIdx.x & 7;
        float v0 = ts[dg * 4 + 0][code];
        float v1 = ts[dg * 4 + 1][code];
        float v2 = ts[dg * 4 + 2][code];
        float v3 = ts[dg * 4 + 3][code];
        size_t o = (size_t)(n0 + code) * DIMS + d0 + dg * 4;
        *(float4*)(g_ebT + o) = make_float4(v0, v1, v2, v3);
        *(uint32_t*)(g_e8 + o) = (uint32_t)f2_e4m3(v0, v1) |
                                 ((uint32_t)f2_e4m3(v2, v3) << 16);
        atomicAdd(&g_enorm[n0 + code], v0 * v0 + v1 * v1 + v2 * v2 + v3 * v3);
    }
}

// ---------------- Phase A: FP8 MMA GEMM + candidate collection (R13) --------
#define AS_OFF   0
#define BS_OFF   (TM * ROWB)
#define BS_SZ    (TN * ROWB)
#define ES_OFF   (BS_OFF + 2 * BS_SZ)
#define MIN_OFF  (ES_OFF + 2 * TN * 4)
#define SMEM_TOT (MIN_OFF + TM * 4)             // 105984

__global__ __launch_bounds__(256, 2) void phaseA_kernel() {
    extern __shared__ __align__(128) char smem[];
    const uint32_t sb = smem_u32(smem);
    uint32_t* smin = (uint32_t*)(smem + MIN_OFF);
    const int tid  = threadIdx.x;
    const int lane = tid & 31;
    const int wid  = tid >> 5;
    const int warpM = wid & 3;
    const int warpN = wid >> 2;
    const int gid  = lane >> 2;
    const int tidg = lane & 3;
    const int m0   = blockIdx.x * TM;
    const int c0   = blockIdx.y * NCHUNK;

    if (tid < TM) smin[tid] = 0xFFFFFFFFu;

    {
#pragma unroll
        for (int j = 0; j < 8; j++) {
            int i = tid + j * 256;
            int r = i >> 4, c = i & 15;
            cp_async16(sb + AS_OFF + r * ROWB + c * 16,
                       g_x8 + (size_t)(m0 + r) * 256 + c * 16);
        }
#pragma unroll
        for (int j = 0; j < 8; j++) {
            int i = tid + j * 256;
            int r = i >> 4, c = i & 15;
            cp_async16(sb + BS_OFF + r * ROWB + c * 16,
                       g_e8 + (size_t)c0 * TN * 256 + (size_t)r * 256 + c * 16);
        }
        if (tid < 32)
            cp_async16(sb + ES_OFF + tid * 16,
                       (const char*)(g_enorm + c0 * TN) + tid * 16);
        cp_commit();
    }

    uint32_t addrA[2];
#pragma unroll
    for (int mt = 0; mt < 2; mt++) {
        int r = warpM * 32 + mt * 16 + ((lane >> 3) & 1) * 8 + (lane & 7);
        addrA[mt] = sb + AS_OFF + r * ROWB + ((lane >> 4) * 16);
    }
    uint32_t rowoffB[4];
#pragma unroll
    for (int g = 0; g < 4; g++) {
        int r = warpN * 64 + g * 16 + (lane >> 4) * 8 + (lane & 7);
        rowoffB[g] = r * ROWB + ((lane >> 3) & 1) * 16;
    }

    const int tl0 = warpM * 32 + gid;

    for (int s = 0; s < NCHUNK; s++) {
        cp_wait0();
        __syncthreads();

        if (s + 1 < NCHUNK) {
            const uint8_t* bsrc = g_e8 + (size_t)(c0 + s + 1) * TN * 256;
            uint32_t bdst = sb + BS_OFF + ((s + 1) & 1) * BS_SZ;
#pragma unroll
            for (int j = 0; j < 8; j++) {
                int i = tid + j * 256;
                int r = i >> 4, c = i & 15;
                cp_async16(bdst + r * ROWB + c * 16, bsrc + (size_t)r * 256 + c * 16);
            }
            if (tid < 32)
                cp_async16(sb + ES_OFF + ((s + 1) & 1) * 512 + tid * 16,
                           (const char*)(g_enorm + (size_t)(c0 + s + 1) * TN) + tid * 16);
            cp_commit();
        }

        const int b = s & 1;
        const uint32_t bbase = sb + BS_OFF + b * BS_SZ;

        float acc[2][8][4];
#pragma unroll
        for (int mt = 0; mt < 2; mt++)
#pragma unroll
            for (int nt = 0; nt < 8; nt++)
#pragma unroll
                for (int q = 0; q < 4; q++) acc[mt][nt][q] = 0.0f;

#pragma unroll
        for (int k = 0; k < 8; k++) {
            uint32_t afr[2][4], bfr[4][4];
            ldsm_x4(afr[0], addrA[0] + k * 32);
            ldsm_x4(afr[1], addrA[1] + k * 32);
#pragma unroll
            for (int g = 0; g < 4; g++)
                ldsm_x4(bfr[g], bbase + rowoffB[g] + k * 32);
#pragma unroll
            for (int mt = 0; mt < 2; mt++)
#pragma unroll
                for (int nt = 0; nt < 8; nt++)
                    mma_fp8(acc[mt][nt], afr[mt],
                            bfr[nt >> 1][(nt & 1) * 2],
                            bfr[nt >> 1][(nt & 1) * 2 + 1]);
        }

        // ---- single-pass epilogue: in-place scores + lagged prefix-min ----
        const float2* ep = (const float2*)(smem + ES_OFF + b * 512);
        float cmin[2][2];
        cmin[0][0] = cmin[0][1] = cmin[1][0] = cmin[1][1] = FLT_MAX;
#pragma unroll
        for (int nt = 0; nt < 8; nt++) {
            const float2 e = ep[(warpN * 64 + nt * 8 + tidg * 2) >> 1];
#pragma unroll
            for (int mt = 0; mt < 2; mt++) {
                float s00 = fmaf(-2.0f, acc[mt][nt][0], e.x);
                float s01 = fmaf(-2.0f, acc[mt][nt][1], e.y);
                float s10 = fmaf(-2.0f, acc[mt][nt][2], e.x);
                float s11 = fmaf(-2.0f, acc[mt][nt][3], e.y);
                acc[mt][nt][0] = s00; acc[mt][nt][1] = s01;
                acc[mt][nt][2] = s10; acc[mt][nt][3] = s11;
                cmin[mt][0] = fminf(cmin[mt][0], fminf(s00, s01));
                cmin[mt][1] = fminf(cmin[mt][1], fminf(s10, s11));
            }
        }
        float wmin[2][2];
#pragma unroll
        for (int mt = 0; mt < 2; mt++)
#pragma unroll
            for (int h = 0; h < 2; h++) {
                float v = cmin[mt][h];
                v = fminf(v, __shfl_xor_sync(0xffffffffu, v, 1));
                v = fminf(v, __shfl_xor_sync(0xffffffffu, v, 2));
                wmin[mt][h] = v;
                if (tidg == 0) {
                    const int tl = tl0 + mt * 16 + h * 8;
                    const uint32_t u = encf(v);
                    if (u < smin[tl]) atomicMin(&smin[tl], u);
                }
            }
        if (s == 0) __syncthreads();   // exact threshold for first chunk

        const int cgb = (c0 + s) * TN + warpN * 64 + tidg * 2;
#pragma unroll
        for (int mt = 0; mt < 2; mt++) {
            const int t0 = m0 + tl0 + mt * 16;
            const int t1 = t0 + 8;
            const float thr0 =
                fminf(decf(smin[tl0 + mt * 16]), wmin[mt][0]) + MARGIN;
            const float thr1 =
                fminf(decf(smin[tl0 + mt * 16 + 8]), wmin[mt][1]) + MARGIN;

            if (cmin[mt][0] <= thr0) {
#pragma unroll
                for (int nt = 0; nt < 8; nt++) {
                    if (fminf(acc[mt][nt][0], acc[mt][nt][1]) <= thr0) {
                        const int cg = cgb + nt * 8;
                        if (acc[mt][nt][0] <= thr0) {
                            int pos = atomicAdd(&g_ccnt[t0], 1);
                            if (pos < CAP) { g_cs[(size_t)t0 * CAP + pos] = acc[mt][nt][0];
                                             g_ci[(size_t)t0 * CAP + pos] = cg; }
                        }
                        if (acc[mt][nt][1] <= thr0) {
                            int pos = atomicAdd(&g_ccnt[t0], 1);
                            if (pos < CAP) { g_cs[(size_t)t0 * CAP + pos] = acc[mt][nt][1];
                                             g_ci[(size_t)t0 * CAP + pos] = cg + 1; }
                        }
                    }
                }
            }
            if (cmin[mt][1] <= thr1) {
#pragma unroll
                for (int nt = 0; nt < 8; nt++) {
                    if (fminf(acc[mt][nt][2], acc[mt][nt][3]) <= thr1) {
                        const int cg = cgb + nt * 8;
                        if (acc[mt][nt][2] <= thr1) {
                            int pos = atomicAdd(&g_ccnt[t1], 1);
                            if (pos < CAP) { g_cs[(size_t)t1 * CAP + pos] = acc[mt][nt][2];
                                             g_ci[(size_t)t1 * CAP + pos] = cg; }
                        }
                        if (acc[mt][nt][3] <= thr1) {
                            int pos = atomicAdd(&g_ccnt[t1], 1);
                            if (pos < CAP) { g_cs[(size_t)t1 * CAP + pos] = acc[mt][nt][3];
                                             g_ci[(size_t)t1 * CAP + pos] = cg + 1; }
                        }
                    }
                }
            }
        }
    }

    // publish per-token approx min (phaseC pruning threshold)
    __syncthreads();
    if (tid < TM) {
        uint32_t u = smin[tid];
        if (u < g_gmin[m0 + tid]) atomicMin(&g_gmin[m0 + tid], u);
    }
}

// ---------------- Phase C: parallel prune + exact rescore + scatter ---------
__global__ __launch_bounds__(256) void phaseC_kernel(
    const float* __restrict__ x, float* __restrict__ out)
{
    __shared__ float blk_diff;
    __shared__ int surv[8][SURV];
    const int lane = threadIdx.x & 31;
    const int w = threadIdx.x >> 5;
    const int t = blockIdx.x * 8 + w;

    if (threadIdx.x == 0) blk_diff = 0.0f;
    __syncthreads();

    float xr[8];
    *(float4*)(xr)     = *(const float4*)(x + (size_t)t * DIMS + lane * 8);
    *(float4*)(xr + 4) = *(const float4*)(x + (size_t)t * DIMS + lane * 8 + 4);

    const int n = g_ccnt[t];
    float bs = FLT_MAX;
    int bi = NE;
    bool fallback = (n > CAP);
    int cnt = 0;

    if (!fallback) {
        // parallel prune: 32 lanes test strided candidates, ballot-compact
        const float thr = decf(g_gmin[t]) + MARGIN;
        const float* cs = g_cs + (size_t)t * CAP;
        const int*   ci = g_ci + (size_t)t * CAP;
        for (int base = 0; base < n; base += 32) {
            const int i = base + lane;
            const bool act = i < n;
            const float sv = act ? cs[i] : FLT_MAX;
            const bool keep = act && (sv <= thr);
            const int kv = keep ? ci[i] : 0;
            const uint32_t mask = __ballot_sync(0xffffffffu, keep);
            const int idx = cnt + __popc(mask & ((1u << lane) - 1));
            if (keep && idx < SURV) surv[w][idx] = kv;
            cnt += __popc(mask);
        }
        if (cnt > SURV) fallback = true;
        __syncwarp();
    }

    if (fallback) {
        // exhaustive exact scan (probabilistically unreachable)
        for (int k = lane; k < NE; k += 32) {
            const float* er = g_ebT + (size_t)k * DIMS;
            const float* xp = x + (size_t)t * DIMS;
            float dot = 0.0f;
            for (int d = 0; d < DIMS; d += 4) {
                float4 xv = *(const float4*)(xp + d);
                float4 ev = *(const float4*)(er + d);
                dot += xv.x * ev.x + xv.y * ev.y + xv.z * ev.z + xv.w * ev.w;
            }
            float s = g_enorm[k] - 2.0f * dot;
            if (s < bs || (s == bs && k < bi)) { bs = s; bi = k; }
        }
        for (int off = 16; off; off >>= 1) {
            float ov = __shfl_xor_sync(0xffffffffu, bs, off);
            int oi = __shfl_xor_sync(0xffffffffu, bi, off);
            if (ov < bs || (ov == bs && oi < bi)) { bs = ov; bi = oi; }
        }
    } else if (cnt == 1) {
        // single survivor IS the argmin — no exact rescore needed
        bi = surv[w][0];
    } else {
        // warp-cooperative exact dot on each survivor (~2-5 per token)
        for (int j = 0; j < cnt; j++) {
            const int k = surv[w][j];
            const float* er = g_ebT + (size_t)k * DIMS + lane * 8;
            float4 e0 = *(const float4*)(er);
            float4 e1 = *(const float4*)(er + 4);
            float d = xr[0] * e0.x + xr[1] * e0.y + xr[2] * e0.z + xr[3] * e0.w
                    + xr[4] * e1.x + xr[5] * e1.y + xr[6] * e1.z + xr[7] * e1.w;
            for (int off = 16; off; off >>= 1)
                d += __shfl_xor_sync(0xffffffffu, d, off);
            float s = g_enorm[k] - 2.0f * d;
            if (s < bs || (s == bs && k < bi)) { bs = s; bi = k; }
        }
    }

    // ---- fused scatter: quantize row, diff, onehot, embed_sum, ind ----
    const float* qr = g_ebT + (size_t)bi * DIMS + lane * 8;
    float4 q0 = *(const float4*)(qr);
    float4 q1 = *(const float4*)(qr + 4);
    *(float4*)(out + OFF_Q + (size_t)t * DIMS + lane * 8)     = q0;
    *(float4*)(out + OFF_Q + (size_t)t * DIMS + lane * 8 + 4) = q1;

    float qv[8] = {q0.x, q0.y, q0.z, q0.w, q1.x, q1.y, q1.z, q1.w};
    float dp = 0.0f;
#pragma unroll
    for (int j = 0; j < 8; j++) {
        float dd = qv[j] - xr[j];
        dp += dd * dd;
        atomicAdd(out + OFF_ES + (size_t)(lane * 8 + j) * NE + bi, xr[j]);
    }
    for (int off = 16; off; off >>= 1)
        dp += __shfl_down_sync(0xffffffffu, dp, off);
    if (lane == 0) {
        atomicAdd(&blk_diff, dp);
        atomicAdd(out + OFF_OH + bi, 1.0f);
        out[OFF_IND + t] = (float)bi;
    }
    __syncthreads();
    if (threadIdx.x == 0)
        atomicAdd(out + OFF_DIFF, blk_diff * (1.0f / (float)(NTOK * DIMS)));
}

// ---------------------------------------------------------------------------
extern "C" void kernel_launch(void* const* d_in, const int* in_sizes, int n_in,
                              void* d_out, int out_size)
{
    const float* x = (const float*)d_in[0];
    const float* embed = (const float*)d_in[1];
    if (n_in >= 2 && in_sizes[0] == DIMS * NE && in_sizes[1] == NTOK * DIMS) {
        const float* tmp = x; x = embed; embed = tmp;
    }
    float* out = (float*)d_out;

    cudaFuncSetAttribute(phaseA_kernel,
                         cudaFuncAttributeMaxDynamicSharedMemorySize, SMEM_TOT);

    prep_kernel<<<CONV_BLKS + 2048, 256>>>(x, embed, out);
    phaseA_kernel<<<dim3(NTOK / TM, NSPLIT), 256, SMEM_TOT>>>();
    phaseC_kernel<<<NTOK / 8, 256>>>(x, out);
}

// round 16
// speedup vs baseline: 1.0592x; 1.0028x over previous
#include <cuda_runtime.h>
#include <cuda_bf16.h>
#include <cstdint>
#include <float.h>

#define DIMS 256
#define NE   8192
#define NTOK 16384

// Output layout (float32, concatenated in reference return order)
#define OFF_Q    0
#define OFF_DIFF 4194304
#define OFF_IND  4194305
#define OFF_OH   4210689
#define OFF_ES   4218881
#define OUT_TOT  6316033

#define CAP    512
#define SURV   64
#define MARGIN 12.0f

// Phase A tiling (fp8) — R8/R13 geometry (365.5us champion, untouched)
#define TM     128
#define TN     128
#define NSPLIT 2
#define NCHUNK (NE / TN / NSPLIT)   // 32
#define ROWB   272

// Phase C: 16 warps per block
#define PCW 16

// ---------------- device scratch (static, no runtime allocs) ----------------
__device__ uint8_t  g_x8[NTOK * DIMS];
__device__ uint8_t  g_e8[NE * DIMS];
__device__ float    g_ebT[NE * DIMS];
__device__ float    g_enorm[NE];
__device__ int      g_ccnt[NTOK];
__device__ uint32_t g_gmin[NTOK];              // encoded approx global min
__device__ float    g_cs[(size_t)NTOK * CAP];
__device__ int      g_ci[(size_t)NTOK * CAP];

// ---------------- baseline-PTX helpers --------------------------------------
__device__ __forceinline__ uint32_t smem_u32(const void* p) {
    uint32_t a;
    asm("{ .reg .u64 t; cvta.to.shared.u64 t, %1; cvt.u32.u64 %0, t; }"
        : "=r"(a) : "l"(p));
    return a;
}
__device__ __forceinline__ void cp_async16(uint32_t dst, const void* src) {
    asm volatile("cp.async.cg.shared.global [%0], [%1], 16;"
                 :: "r"(dst), "l"(src) : "memory");
}
__device__ __forceinline__ void cp_commit() {
    asm volatile("cp.async.commit_group;" ::: "memory");
}
__device__ __forceinline__ void cp_wait0() {
    asm volatile("cp.async.wait_group 0;" ::: "memory");
}
__device__ __forceinline__ void ldsm_x4(uint32_t* r, uint32_t addr) {
    asm volatile("ldmatrix.sync.aligned.m8n8.x4.shared.b16 {%0,%1,%2,%3}, [%4];"
                 : "=r"(r[0]), "=r"(r[1]), "=r"(r[2]), "=r"(r[3]) : "r"(addr));
}
__device__ __forceinline__ void mma_fp8(float* c, const uint32_t* a,
                                        uint32_t b0, uint32_t b1) {
    asm volatile(
        "mma.sync.aligned.m16n8k32.row.col.f32.e4m3.e4m3.f32 "
        "{%0,%1,%2,%3}, {%4,%5,%6,%7}, {%8,%9}, {%0,%1,%2,%3};"
        : "+f"(c[0]), "+f"(c[1]), "+f"(c[2]), "+f"(c[3])
        : "r"(a[0]), "r"(a[1]), "r"(a[2]), "r"(a[3]), "r"(b0), "r"(b1));
}
__device__ __forceinline__ uint16_t f2_e4m3(float lo, float hi) {
    uint16_t r;
    asm("cvt.rn.satfinite.e4m3x2.f32 %0, %1, %2;" : "=h"(r) : "f"(hi), "f"(lo));
    return r;
}
__device__ __forceinline__ uint32_t encf(float f) {
    uint32_t b = __float_as_uint(f);
    return (b & 0x80000000u) ? ~b : (b | 0x80000000u);
}
__device__ __forceinline__ float decf(uint32_t u) {
    uint32_t b = (u & 0x80000000u) ? (u ^ 0x80000000u) : ~u;
    return __uint_as_float(b);
}

// ---------------- fused prep: conv_x + zero-init + transpose ----------------
#define CONV_BLKS 1024
__global__ void prep_kernel(const float* __restrict__ x,
                            const float* __restrict__ embed,
                            float* __restrict__ out) {
    if (blockIdx.x < CONV_BLKS) {
        const int gtid = blockIdx.x * blockDim.x + threadIdx.x;
        const int gstride = CONV_BLKS * blockDim.x;
        size_t i = (size_t)gtid * 16;
        if (i < (size_t)NTOK * DIMS) {
            uint4 o;
            uint32_t* op = (uint32_t*)&o;
#pragma unroll
            for (int j = 0; j < 4; j++) {
                float4 v = *(const float4*)(x + i + j * 4);
                op[j] = (uint32_t)f2_e4m3(v.x, v.y) |
                        ((uint32_t)f2_e4m3(v.z, v.w) << 16);
            }
            *(uint4*)(g_x8 + i) = o;
        }
        for (int j = gtid; j < OUT_TOT - OFF_DIFF; j += gstride)
            out[OFF_DIFF + j] = 0.0f;
        for (int j = gtid; j < NTOK; j += gstride) {
            g_ccnt[j] = 0;
            g_gmin[j] = 0xFFFFFFFFu;
        }
        for (int j = gtid; j < NE; j += gstride) g_enorm[j] = 0.0f;
    } else {
        __shared__ float ts[32][33];
        const int bb = blockIdx.x - CONV_BLKS;
        const int n0 = (bb & 255) * 32;
        const int d0 = (bb >> 8) * 32;
        const int tx = threadIdx.x & 31;
        const int ty = threadIdx.x >> 5;
        for (int r = ty; r < 32; r += 8)
            ts[r][tx] = embed[(size_t)(d0 + r) * NE + n0 + tx];
        __syncthreads();
        const int code = threadIdx.x >> 3;
        const int dg   = threadIdx.x & 7;
        float v0 = ts[dg * 4 + 0][code];
        float v1 = ts[dg * 4 + 1][code];
        float v2 = ts[dg * 4 + 2][code];
        float v3 = ts[dg * 4 + 3][code];
        size_t o = (size_t)(n0 + code) * DIMS + d0 + dg * 4;
        *(float4*)(g_ebT + o) = make_float4(v0, v1, v2, v3);
        *(uint32_t*)(g_e8 + o) = (uint32_t)f2_e4m3(v0, v1) |
                                 ((uint32_t)f2_e4m3(v2, v3) << 16);
        atomicAdd(&g_enorm[n0 + code], v0 * v0 + v1 * v1 + v2 * v2 + v3 * v3);
    }
}

// ---------------- Phase A: FP8 MMA GEMM + candidate collection (R13) --------
#define AS_OFF   0
#define BS_OFF   (TM * ROWB)
#define BS_SZ    (TN * ROWB)
#define ES_OFF   (BS_OFF + 2 * BS_SZ)
#define MIN_OFF  (ES_OFF + 2 * TN * 4)
#define SMEM_TOT (MIN_OFF + TM * 4)             // 105984

__global__ __launch_bounds__(256, 2) void phaseA_kernel() {
    extern __shared__ __align__(128) char smem[];
    const uint32_t sb = smem_u32(smem);
    uint32_t* smin = (uint32_t*)(smem + MIN_OFF);
    const int tid  = threadIdx.x;
    const int lane = tid & 31;
    const int wid  = tid >> 5;
    const int warpM = wid & 3;
    const int warpN = wid >> 2;
    const int gid  = lane >> 2;
    const int tidg = lane & 3;
    const int m0   = blockIdx.x * TM;
    const int c0   = blockIdx.y * NCHUNK;

    if (tid < TM) smin[tid] = 0xFFFFFFFFu;

    {
#pragma unroll
        for (int j = 0; j < 8; j++) {
            int i = tid + j * 256;
            int r = i >> 4, c = i & 15;
            cp_async16(sb + AS_OFF + r * ROWB + c * 16,
                       g_x8 + (size_t)(m0 + r) * 256 + c * 16);
        }
#pragma unroll
        for (int j = 0; j < 8; j++) {
            int i = tid + j * 256;
            int r = i >> 4, c = i & 15;
            cp_async16(sb + BS_OFF + r * ROWB + c * 16,
                       g_e8 + (size_t)c0 * TN * 256 + (size_t)r * 256 + c * 16);
        }
        if (tid < 32)
            cp_async16(sb + ES_OFF + tid * 16,
                       (const char*)(g_enorm + c0 * TN) + tid * 16);
        cp_commit();
    }

    uint32_t addrA[2];
#pragma unroll
    for (int mt = 0; mt < 2; mt++) {
        int r = warpM * 32 + mt * 16 + ((lane >> 3) & 1) * 8 + (lane & 7);
        addrA[mt] = sb + AS_OFF + r * ROWB + ((lane >> 4) * 16);
    }
    uint32_t rowoffB[4];
#pragma unroll
    for (int g = 0; g < 4; g++) {
        int r = warpN * 64 + g * 16 + (lane >> 4) * 8 + (lane & 7);
        rowoffB[g] = r * ROWB + ((lane >> 3) & 1) * 16;
    }

    const int tl0 = warpM * 32 + gid;

    for (int s = 0; s < NCHUNK; s++) {
        cp_wait0();
        __syncthreads();

        if (s + 1 < NCHUNK) {
            const uint8_t* bsrc = g_e8 + (size_t)(c0 + s + 1) * TN * 256;
            uint32_t bdst = sb + BS_OFF + ((s + 1) & 1) * BS_SZ;
#pragma unroll
            for (int j = 0; j < 8; j++) {
                int i = tid + j * 256;
                int r = i >> 4, c = i & 15;
                cp_async16(bdst + r * ROWB + c * 16, bsrc + (size_t)r * 256 + c * 16);
            }
            if (tid < 32)
                cp_async16(sb + ES_OFF + ((s + 1) & 1) * 512 + tid * 16,
                           (const char*)(g_enorm + (size_t)(c0 + s + 1) * TN) + tid * 16);
            cp_commit();
        }

        const int b = s & 1;
        const uint32_t bbase = sb + BS_OFF + b * BS_SZ;

        float acc[2][8][4];
#pragma unroll
        for (int mt = 0; mt < 2; mt++)
#pragma unroll
            for (int nt = 0; nt < 8; nt++)
#pragma unroll
                for (int q = 0; q < 4; q++) acc[mt][nt][q] = 0.0f;

#pragma unroll
        for (int k = 0; k < 8; k++) {
            uint32_t afr[2][4], bfr[4][4];
            ldsm_x4(afr[0], addrA[0] + k * 32);
            ldsm_x4(afr[1], addrA[1] + k * 32);
#pragma unroll
            for (int g = 0; g < 4; g++)
                ldsm_x4(bfr[g], bbase + rowoffB[g] + k * 32);
#pragma unroll
            for (int mt = 0; mt < 2; mt++)
#pragma unroll
                for (int nt = 0; nt < 8; nt++)
                    mma_fp8(acc[mt][nt], afr[mt],
                            bfr[nt >> 1][(nt & 1) * 2],
                            bfr[nt >> 1][(nt & 1) * 2 + 1]);
        }

        // ---- single-pass epilogue: in-place scores + lagged prefix-min ----
        const float2* ep = (const float2*)(smem + ES_OFF + b * 512);
        float cmin[2][2];
        cmin[0][0] = cmin[0][1] = cmin[1][0] = cmin[1][1] = FLT_MAX;
#pragma unroll
        for (int nt = 0; nt < 8; nt++) {
            const float2 e = ep[(warpN * 64 + nt * 8 + tidg * 2) >> 1];
#pragma unroll
            for (int mt = 0; mt < 2; mt++) {
                float s00 = fmaf(-2.0f, acc[mt][nt][0], e.x);
                float s01 = fmaf(-2.0f, acc[mt][nt][1], e.y);
                float s10 = fmaf(-2.0f, acc[mt][nt][2], e.x);
                float s11 = fmaf(-2.0f, acc[mt][nt][3], e.y);
                acc[mt][nt][0] = s00; acc[mt][nt][1] = s01;
                acc[mt][nt][2] = s10; acc[mt][nt][3] = s11;
                cmin[mt][0] = fminf(cmin[mt][0], fminf(s00, s01));
                cmin[mt][1] = fminf(cmin[mt][1], fminf(s10, s11));
            }
        }
        float wmin[2][2];
#pragma unroll
        for (int mt = 0; mt < 2; mt++)
#pragma unroll
            for (int h = 0; h < 2; h++) {
                float v = cmin[mt][h];
                v = fminf(v, __shfl_xor_sync(0xffffffffu, v, 1));
                v = fminf(v, __shfl_xor_sync(0xffffffffu, v, 2));
                wmin[mt][h] = v;
                if (tidg == 0) {
                    const int tl = tl0 + mt * 16 + h * 8;
                    const uint32_t u = encf(v);
                    if (u < smin[tl]) atomicMin(&smin[tl], u);
                }
            }
        if (s == 0) __syncthreads();   // exact threshold for first chunk

        const int cgb = (c0 + s) * TN + warpN * 64 + tidg * 2;
#pragma unroll
        for (int mt = 0; mt < 2; mt++) {
            const int t0 = m0 + tl0 + mt * 16;
            const int t1 = t0 + 8;
            const float thr0 =
                fminf(decf(smin[tl0 + mt * 16]), wmin[mt][0]) + MARGIN;
            const float thr1 =
                fminf(decf(smin[tl0 + mt * 16 + 8]), wmin[mt][1]) + MARGIN;

            if (cmin[mt][0] <= thr0) {
#pragma unroll
                for (int nt = 0; nt < 8; nt++) {
                    if (fminf(acc[mt][nt][0], acc[mt][nt][1]) <= thr0) {
                        const int cg = cgb + nt * 8;
                        if (acc[mt][nt][0] <= thr0) {
                            int pos = atomicAdd(&g_ccnt[t0], 1);
                            if (pos < CAP) { g_cs[(size_t)t0 * CAP + pos] = acc[mt][nt][0];
                                             g_ci[(size_t)t0 * CAP + pos] = cg; }
                        }
                        if (acc[mt][nt][1] <= thr0) {
                            int pos = atomicAdd(&g_ccnt[t0], 1);
                            if (pos < CAP) { g_cs[(size_t)t0 * CAP + pos] = acc[mt][nt][1];
                                             g_ci[(size_t)t0 * CAP + pos] = cg + 1; }
                        }
                    }
                }
            }
            if (cmin[mt][1] <= thr1) {
#pragma unroll
                for (int nt = 0; nt < 8; nt++) {
                    if (fminf(acc[mt][nt][2], acc[mt][nt][3]) <= thr1) {
                        const int cg = cgb + nt * 8;
                        if (acc[mt][nt][2] <= thr1) {
                            int pos = atomicAdd(&g_ccnt[t1], 1);
                            if (pos < CAP) { g_cs[(size_t)t1 * CAP + pos] = acc[mt][nt][2];
                                             g_ci[(size_t)t1 * CAP + pos] = cg; }
                        }
                        if (acc[mt][nt][3] <= thr1) {
                            int pos = atomicAdd(&g_ccnt[t1], 1);
                            if (pos < CAP) { g_cs[(size_t)t1 * CAP + pos] = acc[mt][nt][3];
                                             g_ci[(size_t)t1 * CAP + pos] = cg + 1; }
                        }
                    }
                }
            }
        }
    }

    // publish per-token approx min (phaseC pruning threshold)
    __syncthreads();
    if (tid < TM) {
        uint32_t u = smin[tid];
        if (u < g_gmin[m0 + tid]) atomicMin(&g_gmin[m0 + tid], u);
    }
}

// ---------------- Phase C: parallel prune + exact rescore + scatter ---------
__global__ __launch_bounds__(PCW * 32) void phaseC_kernel(
    const float* __restrict__ x, float* __restrict__ out)
{
    __shared__ float blk_diff;
    __shared__ int surv[PCW][SURV];
    const int lane = threadIdx.x & 31;
    const int w = threadIdx.x >> 5;
    const int t = blockIdx.x * PCW + w;

    if (threadIdx.x == 0) blk_diff = 0.0f;
    __syncthreads();

    float xr[8];
    *(float4*)(xr)     = *(const float4*)(x + (size_t)t * DIMS + lane * 8);
    *(float4*)(xr + 4) = *(const float4*)(x + (size_t)t * DIMS + lane * 8 + 4);

    const int n = g_ccnt[t];
    float bs = FLT_MAX;
    int bi = NE;
    bool fallback = (n > CAP);
    int cnt = 0;

    if (!fallback) {
        // parallel prune: 32 lanes test strided candidates, ballot-compact
        const float thr = decf(g_gmin[t]) + MARGIN;
        const float* cs = g_cs + (size_t)t * CAP;
        const int*   ci = g_ci + (size_t)t * CAP;
        for (int base = 0; base < n; base += 32) {
            const int i = base + lane;
            const bool act = i < n;
            const float sv = act ? cs[i] : FLT_MAX;
            const bool keep = act && (sv <= thr);
            const int kv = keep ? ci[i] : 0;
            const uint32_t mask = __ballot_sync(0xffffffffu, keep);
            const int idx = cnt + __popc(mask & ((1u << lane) - 1));
            if (keep && idx < SURV) surv[w][idx] = kv;
            cnt += __popc(mask);
        }
        if (cnt > SURV) fallback = true;
        __syncwarp();
    }

    if (fallback) {
        // exhaustive exact scan (probabilistically unreachable)
        for (int k = lane; k < NE; k += 32) {
            const float* er = g_ebT + (size_t)k * DIMS;
            const float* xp = x + (size_t)t * DIMS;
            float dot = 0.0f;
            for (int d = 0; d < DIMS; d += 4) {
                float4 xv = *(const float4*)(xp + d);
                float4 ev = *(const float4*)(er + d);
                dot += xv.x * ev.x + xv.y * ev.y + xv.z * ev.z + xv.w * ev.w;
            }
            float s = g_enorm[k] - 2.0f * dot;
            if (s < bs || (s == bs && k < bi)) { bs = s; bi = k; }
        }
        for (int off = 16; off; off >>= 1) {
            float ov = __shfl_xor_sync(0xffffffffu, bs, off);
            int oi = __shfl_xor_sync(0xffffffffu, bi, off);
            if (ov < bs || (ov == bs && oi < bi)) { bs = ov; bi = oi; }
        }
    } else if (cnt == 1) {
        // single survivor IS the argmin — no exact rescore needed
        bi = surv[w][0];
    } else {
        // warp-cooperative exact dot on each survivor (~2-5 per token)
        for (int j = 0; j < cnt; j++) {
            const int k = surv[w][j];
            const float* er = g_ebT + (size_t)k * DIMS + lane * 8;
            float4 e0 = *(const float4*)(er);
            float4 e1 = *(const float4*)(er + 4);
            float d = xr[0] * e0.x + xr[1] * e0.y + xr[2] * e0.z + xr[3] * e0.w
                    + xr[4] * e1.x + xr[5] * e1.y + xr[6] * e1.z + xr[7] * e1.w;
            for (int off = 16; off; off >>= 1)
                d += __shfl_xor_sync(0xffffffffu, d, off);
            float s = g_enorm[k] - 2.0f * d;
            if (s < bs || (s == bs && k < bi)) { bs = s; bi = k; }
        }
    }

    // ---- fused scatter: quantize row, diff, onehot, embed_sum, ind ----
    const float* qr = g_ebT + (size_t)bi * DIMS + lane * 8;
    float4 q0 = *(const float4*)(qr);
    float4 q1 = *(const float4*)(qr + 4);
    *(float4*)(out + OFF_Q + (size_t)t * DIMS + lane * 8)     = q0;
    *(float4*)(out + OFF_Q + (size_t)t * DIMS + lane * 8 + 4) = q1;

    float qv[8] = {q0.x, q0.y, q0.z, q0.w, q1.x, q1.y, q1.z, q1.w};
    float dp = 0.0f;
#pragma unroll
    for (int j = 0; j < 8; j++) {
        float dd = qv[j] - xr[j];
        dp += dd * dd;
        atomicAdd(out + OFF_ES + (size_t)(lane * 8 + j) * NE + bi, xr[j]);
    }
    for (int off = 16; off; off >>= 1)
        dp += __shfl_down_sync(0xffffffffu, dp, off);
    if (lane == 0) {
        atomicAdd(&blk_diff, dp);
        atomicAdd(out + OFF_OH + bi, 1.0f);
        out[OFF_IND + t] = (float)bi;
    }
    __syncthreads();
    if (threadIdx.x == 0)
        atomicAdd(out + OFF_DIFF, blk_diff * (1.0f / (float)(NTOK * DIMS)));
}

// ---------------------------------------------------------------------------
extern "C" void kernel_launch(void* const* d_in, const int* in_sizes, int n_in,
                              void* d_out, int out_size)
{
    const float* x = (const float*)d_in[0];
    const float* embed = (const float*)d_in[1];
    if (n_in >= 2 && in_sizes[0] == DIMS * NE && in_sizes[1] == NTOK * DIMS) {
        const float* tmp = x; x = embed; embed = tmp;
    }
    float* out = (float*)d_out;

    cudaFuncSetAttribute(phaseA_kernel,
                         cudaFuncAttributeMaxDynamicSharedMemorySize, SMEM_TOT);

    prep_kernel<<<CONV_BLKS + 2048, 256>>>(x, embed, out);
    phaseA_kernel<<<dim3(NTOK / TM, NSPLIT), 256, SMEM_TOT>>>();
    phaseC_kernel<<<NTOK / PCW, PCW * 32>>>(x, out);
}